// round 8
// baseline (speedup 1.0000x reference)
#include <cuda_runtime.h>

// knnLoss: fully fused single persistent kernel.
// Phases (separated by hand-rolled grid barriers, 512 co-resident blocks):
//  0 zero hists -> 1 hist(x-bin) -> 2 prefix (block 0) -> 3 counting scatter
//  -> 4 phase A: home-tile scan => per-query top3 bound + per-group tile window
//  -> 5 phase B: 4-way split-k scan of window tiles (pruned partial top3)
//  -> 6 merge (exact) + per-group fixed-point reduce -> 7 final reduce.

#define NPTS   16384
#define NB     2
#define NBINS  512
#define XMIN   (-4.5f)
#define BINSCL (NBINS / 9.0f)
#define WBIN   (9.0f / NBINS)
#define TILE   512
#define NTILES (NPTS / TILE)        // 32
#define QBLK   256                  // queries per group
#define NGRP   (NB * NPTS / QBLK)   // 128
#define SPLIT  4
#define NBLK   (NGRP * SPLIT)       // 512 blocks
#define NTHR   256

__device__ int       g_thist[NB * NBINS];
__device__ int       g_qhist[NB * NBINS];
__device__ int       g_tbase[NB * NBINS];
__device__ int       g_tcur [NB * NBINS];
__device__ int       g_qcur [NB * NBINS];
__device__ float     g_sx[NB * NPTS];
__device__ float     g_sy[NB * NPTS];
__device__ float     g_sz[NB * NPTS];
__device__ float     g_sw[NB * NPTS];
__device__ float4    g_q [NB * NPTS];
__device__ float     g_phome[NB * NPTS * 3];
__device__ float     g_psplit[SPLIT * NB * NPTS * 3];
__device__ int       g_glo[NGRP];
__device__ int       g_ghi[NGRP];
__device__ int       g_ghome[NGRP];
__device__ long long g_psum[NGRP];
__device__ int       g_pcnt[NGRP];
__device__ unsigned          g_barcnt;
__device__ volatile unsigned g_bargen;

#define FMA2(d, a, b, c) \
    asm("fma.rn.f32x2 %0, %1, %2, %3;" : "=l"(d) : "l"(a), "l"(b), "l"(c))
#define UNPK2(lo, hi, v) \
    asm("mov.b64 {%0, %1}, %2;" : "=f"(lo), "=f"(hi) : "l"(v))
#define DUP2(d, f) \
    asm("mov.b64 %0, {%1, %1};" : "=l"(d) : "f"(f))

__device__ __forceinline__ void grid_sync() {
    __syncthreads();
    if (threadIdx.x == 0) {
        unsigned gen = g_bargen;
        __threadfence();
        unsigned rank = atomicAdd(&g_barcnt, 1u);
        if (rank == NBLK - 1) {
            g_barcnt = 0;
            __threadfence();
            g_bargen = gen + 1;
        } else {
            while (g_bargen == gen) { __nanosleep(128); }
        }
        __threadfence();
    }
    __syncthreads();
}

__device__ __forceinline__ int xbin(float x) {
    int b = (int)((x - XMIN) * BINSCL);
    return min(max(b, 0), NBINS - 1);
}

__device__ __forceinline__ void top3_insert(float r, float& b0, float& b1, float& b2) {
    float m1 = fmaxf(r, b1);
    float m0 = fmaxf(r, b0);
    b2 = fminf(b2, m1);
    b1 = fminf(b1, m0);
    b0 = fminf(b0, r);
}

// conservative tile x-bounds (edge bins -> +-inf)
__device__ __forceinline__ void tile_bounds(int b, int t, float& xlo, float& xhi) {
    int binf = xbin(g_sx[b * NPTS + t * TILE]);
    int binl = xbin(g_sx[b * NPTS + t * TILE + TILE - 1]);
    xlo = (binf == 0)         ? -1e30f : XMIN + binf * WBIN;
    xhi = (binl == NBINS - 1) ?  1e30f : XMIN + (binl + 1) * WBIN;
}

__device__ __forceinline__ void scan_tile(
    int base, int tid,
    ulonglong2* s_x, ulonglong2* s_y, ulonglong2* s_z, ulonglong2* s_w,
    unsigned long long qx, unsigned long long qy, unsigned long long qz,
    float& b0, float& b1, float& b2, float& bcap)
{
    const float4* px = (const float4*)(g_sx + base);
    const float4* py = (const float4*)(g_sy + base);
    const float4* pz = (const float4*)(g_sz + base);
    const float4* pw = (const float4*)(g_sw + base);
    if (tid < TILE / 4) {
        float4 vx = px[tid]; s_x[tid] = *(const ulonglong2*)&vx;
        float4 vy = py[tid]; s_y[tid] = *(const ulonglong2*)&vy;
    } else {
        int i2 = tid - TILE / 4;
        float4 vz = pz[i2]; s_z[i2] = *(const ulonglong2*)&vz;
        float4 vw = pw[i2]; s_w[i2] = *(const ulonglong2*)&vw;
    }
    __syncthreads();

#pragma unroll 4
    for (int j = 0; j < TILE / 4; j++) {
        ulonglong2 xv = s_x[j];
        ulonglong2 yv = s_y[j];
        ulonglong2 zv = s_z[j];
        ulonglong2 wv = s_w[j];
        unsigned long long rA, rB;
        FMA2(rA, qx, xv.x, wv.x);
        FMA2(rB, qx, xv.y, wv.y);
        FMA2(rA, qy, yv.x, rA);
        FMA2(rB, qy, yv.y, rB);
        FMA2(rA, qz, zv.x, rA);
        FMA2(rB, qz, zv.y, rB);
        float r0, r1, r2, r3;
        UNPK2(r0, r1, rA);
        UNPK2(r2, r3, rB);
        float m = fminf(fminf(r0, r1), fminf(r2, r3));
        if (m < bcap) {
            top3_insert(r0, b0, b1, b2);
            top3_insert(r1, b0, b1, b2);
            top3_insert(r2, b0, b1, b2);
            top3_insert(r3, b0, b1, b2);
            bcap = fminf(bcap, b2);
        }
    }
    __syncthreads();
}

__global__ __launch_bounds__(NTHR, 4) void fused_kernel(
    const float* __restrict__ src, const float* __restrict__ tgt,
    float* __restrict__ out)
{
    __shared__ char raw[8192];                 // tile SoA / prefix scan overlay
    ulonglong2* s_x = (ulonglong2*)raw;
    ulonglong2* s_y = (ulonglong2*)(raw + 2048);
    ulonglong2* s_z = (ulonglong2*)(raw + 4096);
    ulonglong2* s_w = (ulonglong2*)(raw + 6144);
    int* scan = (int*)raw;

    __shared__ float     stlo[NTILES], sthi[NTILES];
    __shared__ float     sA[NTHR / 32], sB[NTHR / 32];
    __shared__ long long wsum[NTHR / 32];
    __shared__ int       wcnt[NTHR / 32];
    __shared__ int       sh_home;
    __shared__ float     sh_xlo, sh_xhi;
    __shared__ long long rs[NGRP];
    __shared__ int       rc[NGRP];

    int tid = threadIdx.x;
    int bid = blockIdx.x;
    int gi  = bid * NTHR + tid;
    int grp = bid & (NGRP - 1);
    int sp  = bid >> 7;

    // ---- phase 0: zero histograms ----
    if (gi < NB * NBINS)           g_thist[gi] = 0;
    else if (gi < 2 * NB * NBINS)  g_qhist[gi - NB * NBINS] = 0;
    grid_sync();

    // decode this thread's input point indices (reused in phases 1 & 3)
    int pb = gi >> 14;
    int pn = gi & (NPTS - 1);
    int ph = pn >> 9;
    int pw = pn & 511;
    long sOff = (((long)pb * 64 + 2 * ph) * 2048 + 4 * pw) * 3;
    long tOff = (long)pb * 3 * 64 * 2048 + (long)(2 * ph) * 2048 + 4 * pw;

    // ---- phase 1: histogram ----
    if (gi < NB * NPTS) {
        float sx = src[sOff];
        float tx = tgt[tOff];
        atomicAdd(&g_thist[pb * NBINS + xbin(tx)], 1);
        atomicAdd(&g_qhist[pb * NBINS + xbin(sx)], 1);
    }
    grid_sync();

    // ---- phase 2: prefix sums (block 0 only) ----
    if (bid == 0) {
        for (int a = 0; a < 4; a++) {
            const int* h = (a < 2) ? (g_thist + a * NBINS) : (g_qhist + (a - 2) * NBINS);
            int o0 = __ldcg(h + tid);
            int o1 = __ldcg(h + tid + NTHR);
            scan[tid] = o0;
            scan[tid + NTHR] = o1;
            __syncthreads();
            for (int off = 1; off < NBINS; off <<= 1) {
                int v0 = (tid >= off) ? scan[tid - off] : 0;
                int v1 = (tid + NTHR >= off) ? scan[tid + NTHR - off] : 0;
                __syncthreads();
                scan[tid] += v0;
                scan[tid + NTHR] += v1;
                __syncthreads();
            }
            int e0 = scan[tid] - o0;
            int e1 = scan[tid + NTHR] - o1;
            if (a < 2) {
                g_tbase[a * NBINS + tid] = e0;
                g_tbase[a * NBINS + tid + NTHR] = e1;
                g_tcur [a * NBINS + tid] = e0;
                g_tcur [a * NBINS + tid + NTHR] = e1;
            } else {
                g_qcur[(a - 2) * NBINS + tid] = e0;
                g_qcur[(a - 2) * NBINS + tid + NTHR] = e1;
            }
            __syncthreads();
        }
    }
    grid_sync();

    // ---- phase 3: counting scatter ----
    if (gi < NB * NPTS) {
        float tx = tgt[tOff];
        float ty = tgt[tOff + 64 * 2048];
        float tz = tgt[tOff + 2L * 64 * 2048];
        bool  vt = (tx != 0.0f) || (ty != 0.0f) || (tz != 0.0f);
        float tw;
        if (vt) tw = tx * tx + ty * ty + tz * tz;
        else { tx = 0.0f; ty = 0.0f; tz = 0.0f; tw = 1e20f; }
        int tpos = atomicAdd(&g_tcur[pb * NBINS + xbin(tx)], 1);
        int ts = pb * NPTS + tpos;
        g_sx[ts] = tx; g_sy[ts] = ty; g_sz[ts] = tz; g_sw[ts] = tw;

        float sx = src[sOff + 0];
        float sy = src[sOff + 1];
        float sz = src[sOff + 2];
        bool  vs = (sx != 0.0f) || (sy != 0.0f) || (sz != 0.0f);
        float sq = sx * sx + sy * sy + sz * sz;
        int qpos = atomicAdd(&g_qcur[pb * NBINS + xbin(sx)], 1);
        g_q[pb * NPTS + qpos] = make_float4(-2.0f * sx, -2.0f * sy, -2.0f * sz,
                                            vs ? sq : -1.0f);
    }
    grid_sync();

    // per-query state for phases A/B/merge
    int qb = grp >> 6;                                  // batch of this group
    int qi = qb * NPTS + (grp & 63) * QBLK + tid;
    float4 s  = g_q[qi];
    float  xq = -0.5f * s.x;
    bool   valid = (s.w >= 0.0f);
    float  sq = fmaxf(s.w, 0.0f);
    unsigned long long qx, qy, qz;
    DUP2(qx, s.x); DUP2(qy, s.y); DUP2(qz, s.z);
    int lane = tid & 31, warp = tid >> 5;

    // ---- phase 4: home-tile scan + window (blocks with sp==0) ----
    if (sp == 0) {
        if (tid < NTILES) {
            float lo, hi;
            tile_bounds(qb, tid, lo, hi);
            stlo[tid] = lo; sthi[tid] = hi;
        }
        if (tid == NTHR / 2)
            sh_home = min(g_tbase[qb * NBINS + xbin(xq)] >> 9, NTILES - 1);
        __syncthreads();
        int home = sh_home;

        float b0 = 3e38f, b1 = 3e38f, b2 = 3e38f, bcap = 3e38f;
        scan_tile(qb * NPTS + home * TILE, tid, s_x, s_y, s_z, s_w,
                  qx, qy, qz, b0, b1, b2, bcap);

        float rq = sqrtf(fmaxf(b2 + sq, 0.0f));
        float A  = valid ? xq - rq : 1e30f;
        float Bv = valid ? xq + rq : -1e30f;
#pragma unroll
        for (int o = 16; o; o >>= 1) {
            A  = fminf(A,  __shfl_xor_sync(0xffffffffu, A,  o));
            Bv = fmaxf(Bv, __shfl_xor_sync(0xffffffffu, Bv, o));
        }
        if (lane == 0) { sA[warp] = A; sB[warp] = Bv; }
        __syncthreads();
        if (tid == 0) {
            float mA = sA[0], mB = sB[0];
#pragma unroll
            for (int i = 1; i < NTHR / 32; i++) {
                mA = fminf(mA, sA[i]);
                mB = fmaxf(mB, sB[i]);
            }
            int tLo = NTILES, tHi = -1;
            for (int t = 0; t < NTILES; t++)
                if (sthi[t] >= mA) { tLo = t; break; }
            for (int t = NTILES - 1; t >= 0; t--)
                if (stlo[t] <= mB) { tHi = t; break; }
            g_glo[grp] = tLo;
            g_ghi[grp] = tHi;
            g_ghome[grp] = home;
        }
        int o = qi * 3;
        g_phome[o + 0] = b0;
        g_phome[o + 1] = b1;
        g_phome[o + 2] = b2;
    }
    grid_sync();

    // ---- phase 5: split-k windowed scan (all blocks) ----
    {
        float bhome = g_phome[qi * 3 + 2];
        float b0 = 3e38f, b1 = 3e38f, b2 = 3e38f;
        float bcap = bhome;
        int tLo = g_glo[grp], tHi = g_ghi[grp], home = g_ghome[grp];

        for (int t = tLo + sp; t <= tHi; t += SPLIT) {
            if (t == home) continue;
            int base = qb * NPTS + t * TILE;
            if (tid == 0) {
                float lo, hi;
                tile_bounds(qb, t, lo, hi);
                sh_xlo = lo; sh_xhi = hi;
            }
            __syncthreads();
            float xlo = sh_xlo, xhi = sh_xhi;
            float rq = sqrtf(fmaxf(bcap + sq, 0.0f));
            bool need = valid && (xq + rq >= xlo) && (xq - rq <= xhi);
            if (__syncthreads_or(need))
                scan_tile(base, tid, s_x, s_y, s_z, s_w, qx, qy, qz, b0, b1, b2, bcap);
        }
        int o = (sp * NB * NPTS + qi) * 3;
        g_psplit[o + 0] = b0;
        g_psplit[o + 1] = b1;
        g_psplit[o + 2] = b2;
    }
    grid_sync();

    // ---- phase 6: merge + per-group fixed-point reduce (sp==0 blocks) ----
    if (sp == 0) {
        float b0 = g_phome[qi * 3 + 0];
        float b1 = g_phome[qi * 3 + 1];
        float b2 = g_phome[qi * 3 + 2];
#pragma unroll
        for (int k = 0; k < SPLIT; k++) {
            int o = (k * NB * NPTS + qi) * 3;
            top3_insert(__ldcg(&g_psplit[o + 0]), b0, b1, b2);
            top3_insert(__ldcg(&g_psplit[o + 1]), b0, b1, b2);
            top3_insert(__ldcg(&g_psplit[o + 2]), b0, b1, b2);
        }
        float wgt  = valid ? 1.0f : 0.0f;
        float dsum = sqrtf(fmaxf(b0 + sq, 0.0f))
                   + sqrtf(fmaxf(b1 + sq, 0.0f))
                   + sqrtf(fmaxf(b2 + sq, 0.0f));
        long long v = __float2ll_rn(fminf(wgt * dsum, 1e5f) * 4294967296.0f);
#pragma unroll
        for (int o = 16; o; o >>= 1)
            v += __shfl_down_sync(0xffffffffu, v, o);
        int cnt = __popc(__ballot_sync(0xffffffffu, valid));
        if (lane == 0) { wsum[warp] = v; wcnt[warp] = cnt; }
        __syncthreads();
        if (tid == 0) {
            long long vs = 0; int cs = 0;
#pragma unroll
            for (int i = 0; i < NTHR / 32; i++) { vs += wsum[i]; cs += wcnt[i]; }
            g_psum[grp] = vs;
            g_pcnt[grp] = cs;
        }
    }
    grid_sync();

    // ---- phase 7: final reduce (block 0) ----
    if (bid == 0) {
        if (tid < NGRP) {
            rs[tid] = __ldcg(&g_psum[tid]);
            rc[tid] = __ldcg(&g_pcnt[tid]);
        }
        __syncthreads();
        for (int o = 32; o; o >>= 1) {
            if (tid < o) { rs[tid] += rs[tid + o]; rc[tid] += rc[tid + o]; }
            else if (tid >= 64 && tid < 64 + o) {
                rs[tid] += rs[tid + o]; rc[tid] += rc[tid + o];
            }
            __syncthreads();
        }
        if (tid == 0) {
            double S0 = (double)rs[0]  / 4294967296.0;
            double S1 = (double)rs[64] / 4294967296.0;
            float l0 = (float)(S0 / (3.0 * (double)max(rc[0],  1)));
            float l1 = (float)(S1 / (3.0 * (double)max(rc[64], 1)));
            out[0] = 0.5f * (l0 + l1);
        }
    }
}

extern "C" void kernel_launch(void* const* d_in, const int* in_sizes, int n_in,
                              void* d_out, int out_size) {
    const float* src = (const float*)d_in[0];   // source_pc [2,64,2048,3]
    const float* tgt = (const float*)d_in[1];   // target_pc [2,3,64,2048]
    fused_kernel<<<NBLK, NTHR>>>(src, tgt, (float*)d_out);
}